// round 9
// baseline (speedup 1.0000x reference)
#include <cuda_runtime.h>
#include <cuda_fp16.h>
#include <cstdint>

#define TT 16384
#define DD 2048
#define EE 64
#define BR 64                  // rows per CTA
#define NT 256
#define NCH 64                 // K chunks of 32 (full K per CTA)
#define NBUF 3

// ---- smem layout (u32 offsets): per buffer Ahi[64][20] Alo[64][20] B[2048]
#define A_ROW 20
#define A_PLANE (BR * A_ROW)               // 1280
#define BUF_U32 (2 * A_PLANE + 2048)       // 4608
#define AOFF(b, pl) ((b) * BUF_U32 + (pl) * A_PLANE)
#define BOFF(b)     ((b) * BUF_U32 + 2 * A_PLANE)
#define SMEM_U32 (NBUF * BUF_U32)          // 13824
#define SMEM_BYTES (SMEM_U32 * 4)          // 55296 -> 2 CTAs/SM

// epilogue overlay (u32 offsets)
#define SC2 66
#define CNT (BR * SC2)                     // 4224
#define I1A (CNT + 64)
#define I2A (I1A + 64)
#define G1A (I2A + 64)
#define G2A (G1A + 64)

// ---- output layout (floats) ----
#define IDX_OFF  ((size_t)TT * EE)
#define GATE_OFF (IDX_OFF + 2 * (size_t)TT)
#define ACT_OFF  (GATE_OFF + 2 * (size_t)TT)
#define FULL_OUT (ACT_OFF + EE)

// w pre-split to fp16 hi/lo, fragment-major: [k16-step 128][nb 8][lane 32] uint4
// uint4 = {b0_hi, b1_hi, b0_lo, b1_lo}
__device__ uint4 g_w_frag[128 * 8 * 32];

__device__ __forceinline__ uint32_t packh2(__half a, __half b) {
    uint32_t u;
    asm("mov.b32 %0, {%1, %2};" : "=r"(u) : "h"(__half_as_ushort(a)), "h"(__half_as_ushort(b)));
    return u;
}
__device__ __forceinline__ void split_f16(float x, __half& h, __half& l) {
    h = __float2half_rn(x);
    l = __float2half_rn(x - __half2float(h));
}
__device__ __forceinline__ void mma_f16(float* d, const uint32_t* a, uint32_t b0, uint32_t b1) {
    asm volatile(
        "mma.sync.aligned.m16n8k16.row.col.f32.f16.f16.f32 "
        "{%0,%1,%2,%3}, {%4,%5,%6,%7}, {%8,%9}, {%0,%1,%2,%3};"
        : "+f"(d[0]), "+f"(d[1]), "+f"(d[2]), "+f"(d[3])
        : "r"(a[0]), "r"(a[1]), "r"(a[2]), "r"(a[3]), "r"(b0), "r"(b1));
}

#define BAR_ARRIVE(id) asm volatile("bar.arrive %0, %1;" :: "r"(id), "r"(256))
#define BAR_SYNC(id)   asm volatile("bar.sync %0, %1;"   :: "r"(id), "r"(256) : "memory")
#define FULL_B(b) (1 + (b))
#define FREE_B(b) (4 + (b))

// ======================= prep: w -> fragment-major fp16 hi/lo =======================
__global__ void prep_kernel(const float* __restrict__ w, float* __restrict__ out, int we) {
    int t = blockIdx.x * 256 + threadIdx.x;   // 65536 threads, one per u32 pair
    int q = t >> 1, b = t & 1;
    int ks = q >> 8, rem = q & 255, nb = rem >> 5, l = rem & 31;
    int n = nb * 8 + (l >> 2), tig = l & 3;
    int k0 = ks * 16 + 2 * tig + b * 8;
    float w0 = w[(size_t)k0 * EE + n];
    float w1 = w[(size_t)(k0 + 1) * EE + n];
    __half h0, l0, h1, l1;
    split_f16(w0, h0, l0);
    split_f16(w1, h1, l1);
    uint32_t* o32 = (uint32_t*)g_w_frag;
    o32[q * 4 + b]     = packh2(h0, h1);   // hi
    o32[q * 4 + 2 + b] = packh2(l0, l1);   // lo
    if (we && t < EE) out[ACT_OFF + t] = 0.0f;
}

// ======================= main kernel: 256 CTAs x 64 rows, warp-specialized =======================
__global__ __launch_bounds__(NT, 2)
void router_mma_kernel(const float* __restrict__ x,
                       const float* __restrict__ noise,
                       float* __restrict__ out,
                       int write_extras) {
    extern __shared__ uint32_t smu[];
    const int tid = threadIdx.x;
    const int wid = tid >> 5;
    const int lid = tid & 31;
    const int g   = lid >> 2;
    const int t4  = lid & 3;
    const int row0 = blockIdx.x * BR;
    const bool is_consumer = (wid < 4);

    float acc[8][4];
#pragma unroll
    for (int nb = 0; nb < 8; nb++)
#pragma unroll
        for (int i = 0; i < 4; i++) acc[nb][i] = 0.0f;

    if (!is_consumer) {
        // ================= PRODUCER: warps 4..7 =================
        const int pt = tid & 127;
        for (int c = 0; c < NCH; ++c) {
            const int b = c - (c / NBUF) * NBUF;
            // issue gmem loads for chunk c first (latency hidden behind FREE wait)
            float4 xr[4];
            uint4  br[4];
#pragma unroll
            for (int j = 0; j < 4; j++) {
                int flat = pt + 128 * j;            // 512 float4 of x tile (64 rows x 8)
                int r = flat >> 3, kc = flat & 7;
                xr[j] = *(const float4*)(x + (size_t)(row0 + r) * DD + c * 32 + kc * 4);
            }
            const uint4* Bg = g_w_frag + (size_t)c * 512;
#pragma unroll
            for (int j = 0; j < 4; j++) br[j] = Bg[pt + 128 * j];

            if (c >= NBUF) BAR_SYNC(FREE_B(b));

            uint32_t* Ah = smu + AOFF(b, 0);
            uint32_t* Al = smu + AOFF(b, 1);
#pragma unroll
            for (int j = 0; j < 4; j++) {
                int flat = pt + 128 * j;
                int r = flat >> 3, kc = flat & 7;
                float4 v = xr[j];
                __half hx, lx, hy, ly, hz, lz, hw, lw;
                split_f16(v.x, hx, lx); split_f16(v.y, hy, ly);
                split_f16(v.z, hz, lz); split_f16(v.w, hw, lw);
                *(uint2*)(Ah + r * A_ROW + kc * 2) = make_uint2(packh2(hx, hy), packh2(hz, hw));
                *(uint2*)(Al + r * A_ROW + kc * 2) = make_uint2(packh2(lx, ly), packh2(lz, lw));
            }
            uint4* Bs = (uint4*)(smu + BOFF(b));
#pragma unroll
            for (int j = 0; j < 4; j++) Bs[pt + 128 * j] = br[j];

            BAR_ARRIVE(FULL_B(b));
        }
    } else {
        // ================= CONSUMER: warps 0..3, each 16 rows =================
        const int r0 = wid * 16 + g;
        for (int c = 0; c < NCH; ++c) {
            const int b = c - (c / NBUF) * NBUF;
            BAR_SYNC(FULL_B(b));

            const uint32_t* Ah = smu + AOFF(b, 0);
            const uint32_t* Al = smu + AOFF(b, 1);
            const uint4*    Bs = (const uint4*)(smu + BOFF(b));
#pragma unroll
            for (int ks = 0; ks < 2; ks++) {
                const int o = ks * 8 + t4;
                uint32_t ah[4], al[4];
                ah[0] = Ah[r0 * A_ROW + o];
                ah[1] = Ah[(r0 + 8) * A_ROW + o];
                ah[2] = Ah[r0 * A_ROW + o + 4];
                ah[3] = Ah[(r0 + 8) * A_ROW + o + 4];
                al[0] = Al[r0 * A_ROW + o];
                al[1] = Al[(r0 + 8) * A_ROW + o];
                al[2] = Al[r0 * A_ROW + o + 4];
                al[3] = Al[(r0 + 8) * A_ROW + o + 4];
                uint4 bv[8];
#pragma unroll
                for (int nb = 0; nb < 8; nb++) bv[nb] = Bs[(ks * 8 + nb) * 32 + lid];
#pragma unroll
                for (int nb = 0; nb < 8; nb++) mma_f16(acc[nb], ah, bv[nb].x, bv[nb].y);  // h*h
#pragma unroll
                for (int nb = 0; nb < 8; nb++) mma_f16(acc[nb], ah, bv[nb].z, bv[nb].w);  // h*l
#pragma unroll
                for (int nb = 0; nb < 8; nb++) mma_f16(acc[nb], al, bv[nb].x, bv[nb].y);  // l*h
            }
            BAR_ARRIVE(FREE_B(b));
        }
    }

    // ================= epilogue (64 rows) =================
    __syncthreads();
    float* sc = (float*)smu;               // [64][66]
    int*   counts = (int*)(smu + CNT);
    int*   i1a = (int*)(smu + I1A);
    int*   i2a = (int*)(smu + I2A);
    float* g1a = (float*)(smu + G1A);
    float* g2a = (float*)(smu + G2A);

    if (is_consumer) {
        const int r0 = wid * 16 + g;
#pragma unroll
        for (int nb = 0; nb < 8; nb++) {
            int cc = nb * 8 + t4 * 2;
            float2 v0; v0.x = acc[nb][0]; v0.y = acc[nb][1];
            float2 v1; v1.x = acc[nb][2]; v1.y = acc[nb][3];
            *(float2*)(sc + r0 * SC2 + cc)       = v0;
            *(float2*)(sc + (r0 + 8) * SC2 + cc) = v1;
        }
    }
    if (tid < EE) counts[tid] = 0;
    __syncthreads();

    // add noise (coalesced)
#pragma unroll
    for (int j = 0; j < 16; j++) {
        int flat = tid + NT * j;           // 4096 elems
        int r = flat >> 6, e = flat & 63;
        sc[r * SC2 + e] += noise[(size_t)row0 * EE + flat];
    }
    __syncthreads();

    // per-row top-2 + gates (renormalized top-2 softmax == sigmoid of score diff)
    if (tid < BR) {
        const int row = tid;
        const float* p = sc + row * SC2;
        float m1 = -3.402823466e38f, m2 = -3.402823466e38f;
        int b1 = 0, b2 = 0;
#pragma unroll
        for (int e = 0; e < EE; e++) {
            float z = p[e];
            if (z > m1) { m2 = m1; b2 = b1; m1 = z; b1 = e; }
            else if (z > m2) { m2 = z; b2 = e; }
        }
        float e2 = __expf(m2 - m1);
        float inv = 1.0f / (1.0f + e2);
        float g1 = inv, g2 = e2 * inv;
        i1a[row] = b1; i2a[row] = b2; g1a[row] = g1; g2a[row] = g2;
        atomicAdd(&counts[b1], 1);
        atomicAdd(&counts[b2], 1);
        if (write_extras) {
            float2 iv; iv.x = (float)b1; iv.y = (float)b2;
            *(float2*)(out + IDX_OFF + (size_t)(row0 + row) * 2) = iv;
            float2 gv; gv.x = g1; gv.y = g2;
            *(float2*)(out + GATE_OFF + (size_t)(row0 + row) * 2) = gv;
        }
    }
    __syncthreads();

    // combine tensor (float4 coalesced)
#pragma unroll
    for (int j = 0; j < 4; j++) {
        int chunk = tid + NT * j;          // 1024 float4 = 64 rows x 16
        int r = chunk >> 4, c4 = chunk & 15;
        int b1 = i1a[r], b2 = i2a[r];
        float G1 = g1a[r], G2 = g2a[r];
        int cc = c4 * 4;
        float4 v;
        v.x = (cc     == b1) ? G1 : ((cc     == b2) ? G2 : 0.0f);
        v.y = (cc + 1 == b1) ? G1 : ((cc + 1 == b2) ? G2 : 0.0f);
        v.z = (cc + 2 == b1) ? G1 : ((cc + 2 == b2) ? G2 : 0.0f);
        v.w = (cc + 3 == b1) ? G1 : ((cc + 3 == b2) ? G2 : 0.0f);
        *(float4*)(out + (size_t)(row0 + r) * EE + cc) = v;
    }

    if (write_extras && tid < EE) {
        int cnt = counts[tid];
        if (cnt > 0) atomicAdd(out + ACT_OFF + tid, (float)cnt);
    }
}

extern "C" void kernel_launch(void* const* d_in, const int* in_sizes, int n_in,
                              void* d_out, int out_size) {
    const float* x     = (const float*)d_in[0];
    const float* w     = (const float*)d_in[1];
    const float* noise = (const float*)d_in[2];
    float* out = (float*)d_out;

    const int write_extras = ((size_t)out_size >= FULL_OUT) ? 1 : 0;

    cudaFuncSetAttribute(router_mma_kernel,
                         cudaFuncAttributeMaxDynamicSharedMemorySize, SMEM_BYTES);

    prep_kernel<<<256, 256>>>(w, out, write_extras);
    router_mma_kernel<<<TT / BR, NT, SMEM_BYTES>>>(x, noise, out, write_extras);
}

// round 10
// speedup vs baseline: 1.1628x; 1.1628x over previous
#include <cuda_runtime.h>
#include <cuda_fp16.h>
#include <cstdint>

#define TT 16384
#define DD 2048
#define EE 64
#define BM 128
#define NT 512
#define NCH 32                 // chunks of K=32 per K-half
#define NBUF 3

// ---- smem layout (u32 offsets): per set, per buffer: Ahi[128][20] Alo[128][20] B[2048]
#define A_ROW 20
#define A_PLANE (BM * A_ROW)               // 2560
#define BUF_U32 (2 * A_PLANE + 2048)       // 7168
#define SET_U32 (NBUF * BUF_U32)           // 21504
#define AOFF(s,b,pl) ((s)*SET_U32 + (b)*BUF_U32 + (pl)*A_PLANE)
#define BOFF(s,b)    ((s)*SET_U32 + (b)*BUF_U32 + 2*A_PLANE)
#define SMEM_U32 (2 * SET_U32)             // 43008
#define SMEM_BYTES (SMEM_U32 * 4)          // 172032

// epilogue overlay (u32 offsets)
#define SC2 66
#define BOARD_U32 (BM * SC2)               // 8448
#define CNT (2 * BOARD_U32)
#define I1A (CNT + 64)
#define I2A (I1A + 128)
#define G1A (I2A + 128)
#define G2A (G1A + 128)

// ---- output layout (floats) ----
#define IDX_OFF  ((size_t)TT * EE)
#define GATE_OFF (IDX_OFF + 2 * (size_t)TT)
#define ACT_OFF  (GATE_OFF + 2 * (size_t)TT)
#define FULL_OUT (ACT_OFF + EE)

// w pre-split to fp16 hi/lo, fragment-major: [k16-step 128][nb 8][lane 32] uint4
// uint4 = {b0_hi, b1_hi, b0_lo, b1_lo}
__device__ uint4 g_w_frag[128 * 8 * 32];

__device__ __forceinline__ uint32_t packh2(__half a, __half b) {
    uint32_t u;
    asm("mov.b32 %0, {%1, %2};" : "=r"(u) : "h"(__half_as_ushort(a)), "h"(__half_as_ushort(b)));
    return u;
}
__device__ __forceinline__ void split_f16(float x, __half& h, __half& l) {
    h = __float2half_rn(x);
    l = __float2half_rn(x - __half2float(h));
}
__device__ __forceinline__ void mma_f16(float* d, const uint32_t* a, uint32_t b0, uint32_t b1) {
    asm volatile(
        "mma.sync.aligned.m16n8k16.row.col.f32.f16.f16.f32 "
        "{%0,%1,%2,%3}, {%4,%5,%6,%7}, {%8,%9}, {%0,%1,%2,%3};"
        : "+f"(d[0]), "+f"(d[1]), "+f"(d[2]), "+f"(d[3])
        : "r"(a[0]), "r"(a[1]), "r"(a[2]), "r"(a[3]), "r"(b0), "r"(b1));
}
#define BARSET(s) asm volatile("bar.sync %0, %1;" :: "r"((s) + 1), "r"(256) : "memory")

// ======================= prep: w -> fragment-major fp16 hi/lo =======================
__global__ void prep_kernel(const float* __restrict__ w, float* __restrict__ out, int we) {
    int t = blockIdx.x * 256 + threadIdx.x;   // 65536 threads, one per u32 pair
    int q = t >> 1, b = t & 1;
    int ks = q >> 8, rem = q & 255, nb = rem >> 5, l = rem & 31;
    int n = nb * 8 + (l >> 2), tig = l & 3;
    int k0 = ks * 16 + 2 * tig + b * 8;
    float w0 = w[(size_t)k0 * EE + n];
    float w1 = w[(size_t)(k0 + 1) * EE + n];
    __half h0, l0, h1, l1;
    split_f16(w0, h0, l0);
    split_f16(w1, h1, l1);
    uint32_t* o32 = (uint32_t*)g_w_frag;
    o32[q * 4 + b]     = packh2(h0, h1);   // hi
    o32[q * 4 + 2 + b] = packh2(l0, l1);   // lo
    if (we && t < EE) out[ACT_OFF + t] = 0.0f;
}

// ======================= main: uniform warps, 3 buffers, 1 bar/chunk =======================
__global__ __launch_bounds__(NT, 1)
void router_mma_kernel(const float* __restrict__ x,
                       const float* __restrict__ noise,
                       float* __restrict__ out,
                       int write_extras) {
    extern __shared__ uint32_t smu[];
    const int tid = threadIdx.x;
    const int wid = tid >> 5;
    const int lid = tid & 31;
    const int s   = tid >> 8;          // K-half set
    const int st  = tid & 255;
    const int ws  = wid & 7;
    const int g   = lid >> 2;
    const int t4  = lid & 3;
    const int row0 = blockIdx.x * BM;
    const int r0  = ws * 16 + g;       // warp's fragment row

    const size_t xko = (size_t)s * 1024;
    const int wfb = s * 64;            // first k16-step of this half

    // per-thread load/store mapping (x tile: 1024 float4; this thread's 4)
    const int lr[4] = { (st) >> 3, (st + 256) >> 3, (st + 512) >> 3, (st + 768) >> 3 };
    const int lk[4] = { (st) & 7,  (st + 256) & 7,  (st + 512) & 7,  (st + 768) & 7 };

    float acc[8][4];
#pragma unroll
    for (int nb = 0; nb < 8; nb++)
#pragma unroll
        for (int i = 0; i < 4; i++) acc[nb][i] = 0.0f;

    float4 xr[4];                      // regs holding NEXT chunk's x data
    uint4  br[2];                      // regs holding NEXT chunk's B fragments

    // ---- prologue: chunk 0 -> buf0 directly; chunk 1 -> regs ----
    {
#pragma unroll
        for (int j = 0; j < 4; j++)
            xr[j] = *(const float4*)(x + (size_t)(row0 + lr[j]) * DD + xko + lk[j] * 4);
        const uint4* Bg = g_w_frag + (size_t)wfb * 256;
        br[0] = Bg[st]; br[1] = Bg[st + 256];

        uint32_t* Ah = smu + AOFF(s, 0, 0);
        uint32_t* Al = smu + AOFF(s, 0, 1);
#pragma unroll
        for (int j = 0; j < 4; j++) {
            float4 v = xr[j];
            __half hx, lx, hy, ly, hz, lz, hw, lw;
            split_f16(v.x, hx, lx); split_f16(v.y, hy, ly);
            split_f16(v.z, hz, lz); split_f16(v.w, hw, lw);
            *(uint2*)(Ah + lr[j] * A_ROW + lk[j] * 2) = make_uint2(packh2(hx, hy), packh2(hz, hw));
            *(uint2*)(Al + lr[j] * A_ROW + lk[j] * 2) = make_uint2(packh2(lx, ly), packh2(lz, lw));
        }
        uint4* Bs = (uint4*)(smu + BOFF(s, 0));
        Bs[st] = br[0]; Bs[st + 256] = br[1];

        // load chunk 1 into regs
#pragma unroll
        for (int j = 0; j < 4; j++)
            xr[j] = *(const float4*)(x + (size_t)(row0 + lr[j]) * DD + xko + 32 + lk[j] * 4);
        const uint4* Bg1 = g_w_frag + (size_t)(wfb + 2) * 256;
        br[0] = Bg1[st]; br[1] = Bg1[st + 256];
    }
    BARSET(s);

    for (int c = 0; c < NCH; ++c) {
        const int b  = c % NBUF;
        const int bn = (c + 1) % NBUF;
        const uint32_t* Ah = smu + AOFF(s, b, 0);
        const uint32_t* Al = smu + AOFF(s, b, 1);
        const uint4*    Bs = (const uint4*)(smu + BOFF(s, b));

        // ---------- MMA ks=0 ----------
        {
            const int o = t4;
            uint32_t ah[4], al[4];
            ah[0] = Ah[r0 * A_ROW + o];       ah[1] = Ah[(r0 + 8) * A_ROW + o];
            ah[2] = Ah[r0 * A_ROW + o + 4];   ah[3] = Ah[(r0 + 8) * A_ROW + o + 4];
            al[0] = Al[r0 * A_ROW + o];       al[1] = Al[(r0 + 8) * A_ROW + o];
            al[2] = Al[r0 * A_ROW + o + 4];   al[3] = Al[(r0 + 8) * A_ROW + o + 4];
            uint4 bv[8];
#pragma unroll
            for (int nb = 0; nb < 8; nb++) bv[nb] = Bs[nb * 32 + lid];
#pragma unroll
            for (int nb = 0; nb < 8; nb++) mma_f16(acc[nb], ah, bv[nb].x, bv[nb].y);
#pragma unroll
            for (int nb = 0; nb < 8; nb++) mma_f16(acc[nb], ah, bv[nb].z, bv[nb].w);
#pragma unroll
            for (int nb = 0; nb < 8; nb++) mma_f16(acc[nb], al, bv[nb].x, bv[nb].y);
        }

        // ---------- convert next chunk's regs (fills HMMA rt-stall slots) ----------
        uint2 cvh[4], cvl[4];
        if (c + 1 < NCH) {
#pragma unroll
            for (int j = 0; j < 4; j++) {
                float4 v = xr[j];
                __half hx, lx, hy, ly, hz, lz, hw, lw;
                split_f16(v.x, hx, lx); split_f16(v.y, hy, ly);
                split_f16(v.z, hz, lz); split_f16(v.w, hw, lw);
                cvh[j] = make_uint2(packh2(hx, hy), packh2(hz, hw));
                cvl[j] = make_uint2(packh2(lx, ly), packh2(lz, lw));
            }
        }

        // ---------- MMA ks=1 ----------
        {
            const int o = 8 + t4;
            uint32_t ah[4], al[4];
            ah[0] = Ah[r0 * A_ROW + o];       ah[1] = Ah[(r0 + 8) * A_ROW + o];
            ah[2] = Ah[r0 * A_ROW + o + 4];   ah[3] = Ah[(r0 + 8) * A_ROW + o + 4];
            al[0] = Al[r0 * A_ROW + o];       al[1] = Al[(r0 + 8) * A_ROW + o];
            al[2] = Al[r0 * A_ROW + o + 4];   al[3] = Al[(r0 + 8) * A_ROW + o + 4];
            uint4 bv[8];
#pragma unroll
            for (int nb = 0; nb < 8; nb++) bv[nb] = Bs[(8 + nb) * 32 + lid];
#pragma unroll
            for (int nb = 0; nb < 8; nb++) mma_f16(acc[nb], ah, bv[nb].x, bv[nb].y);
#pragma unroll
            for (int nb = 0; nb < 8; nb++) mma_f16(acc[nb], ah, bv[nb].z, bv[nb].w);
#pragma unroll
            for (int nb = 0; nb < 8; nb++) mma_f16(acc[nb], al, bv[nb].x, bv[nb].y);
        }

        // ---------- store converted chunk c+1 into buf bn; prefetch chunk c+2 ----------
        if (c + 1 < NCH) {
            uint32_t* Ahn = smu + AOFF(s, bn, 0);
            uint32_t* Aln = smu + AOFF(s, bn, 1);
#pragma unroll
            for (int j = 0; j < 4; j++) {
                *(uint2*)(Ahn + lr[j] * A_ROW + lk[j] * 2) = cvh[j];
                *(uint2*)(Aln + lr[j] * A_ROW + lk[j] * 2) = cvl[j];
            }
            uint4* Bsn = (uint4*)(smu + BOFF(s, bn));
            Bsn[st] = br[0]; Bsn[st + 256] = br[1];

            const int cn = (c + 2 < NCH) ? c + 2 : c + 1;   // clamp: harmless reload
            const size_t kb = xko + (size_t)cn * 32;
#pragma unroll
            for (int j = 0; j < 4; j++)
                xr[j] = *(const float4*)(x + (size_t)(row0 + lr[j]) * DD + kb + lk[j] * 4);
            const uint4* Bg = g_w_frag + (size_t)(wfb + cn * 2) * 256;
            br[0] = Bg[st]; br[1] = Bg[st + 256];

            BARSET(s);
        }
    }

    // ================= epilogue =================
    __syncthreads();
    float* sc0 = (float*)smu;
    float* sc1 = (float*)(smu + BOARD_U32);
    int*   counts = (int*)(smu + CNT);
    int*   i1a = (int*)(smu + I1A);
    int*   i2a = (int*)(smu + I2A);
    float* g1a = (float*)(smu + G1A);
    float* g2a = (float*)(smu + G2A);

    // scatter accumulators to this half's board
    {
        float* scb = s ? sc1 : sc0;
#pragma unroll
        for (int nb = 0; nb < 8; nb++) {
            int cc = nb * 8 + t4 * 2;
            float2 v0; v0.x = acc[nb][0]; v0.y = acc[nb][1];
            float2 v1; v1.x = acc[nb][2]; v1.y = acc[nb][3];
            *(float2*)(scb + r0 * SC2 + cc)       = v0;
            *(float2*)(scb + (r0 + 8) * SC2 + cc) = v1;
        }
    }
    if (tid < EE) counts[tid] = 0;
    __syncthreads();

    // sum K-halves + noise (coalesced)
#pragma unroll
    for (int j = 0; j < 16; j++) {
        int flat = tid + NT * j;           // 8192 elems
        int r = flat >> 6, e = flat & 63;
        sc0[r * SC2 + e] = sc0[r * SC2 + e] + sc1[r * SC2 + e]
                         + noise[(size_t)row0 * EE + flat];
    }
    __syncthreads();

    // per-row top-2 + gates (renormalized top-2 softmax == sigmoid of score diff)
    if (tid < BM) {
        const int row = tid;
        const float* p = sc0 + row * SC2;
        float m1 = -3.402823466e38f, m2 = -3.402823466e38f;
        int b1 = 0, b2 = 0;
#pragma unroll
        for (int e = 0; e < EE; e++) {
            float z = p[e];
            if (z > m1) { m2 = m1; b2 = b1; m1 = z; b1 = e; }
            else if (z > m2) { m2 = z; b2 = e; }
        }
        float e2 = __expf(m2 - m1);
        float inv = 1.0f / (1.0f + e2);
        float g1 = inv, g2 = e2 * inv;
        i1a[row] = b1; i2a[row] = b2; g1a[row] = g1; g2a[row] = g2;
        atomicAdd(&counts[b1], 1);
        atomicAdd(&counts[b2], 1);
        if (write_extras) {
            float2 iv; iv.x = (float)b1; iv.y = (float)b2;
            *(float2*)(out + IDX_OFF + (size_t)(row0 + row) * 2) = iv;
            float2 gv; gv.x = g1; gv.y = g2;
            *(float2*)(out + GATE_OFF + (size_t)(row0 + row) * 2) = gv;
        }
    }
    __syncthreads();

    // combine tensor (float4 coalesced)
#pragma unroll
    for (int j = 0; j < 4; j++) {
        int chunk = tid + NT * j;          // 2048 float4
        int r = chunk >> 4, c4 = chunk & 15;
        int b1 = i1a[r], b2 = i2a[r];
        float G1 = g1a[r], G2 = g2a[r];
        int cc = c4 * 4;
        float4 v;
        v.x = (cc     == b1) ? G1 : ((cc     == b2) ? G2 : 0.0f);
        v.y = (cc + 1 == b1) ? G1 : ((cc + 1 == b2) ? G2 : 0.0f);
        v.z = (cc + 2 == b1) ? G1 : ((cc + 2 == b2) ? G2 : 0.0f);
        v.w = (cc + 3 == b1) ? G1 : ((cc + 3 == b2) ? G2 : 0.0f);
        *(float4*)(out + (size_t)(row0 + r) * EE + cc) = v;
    }

    if (write_extras && tid < EE) {
        int cnt = counts[tid];
        if (cnt > 0) atomicAdd(out + ACT_OFF + tid, (float)cnt);
    }
}

extern "C" void kernel_launch(void* const* d_in, const int* in_sizes, int n_in,
                              void* d_out, int out_size) {
    const float* x     = (const float*)d_in[0];
    const float* w     = (const float*)d_in[1];
    const float* noise = (const float*)d_in[2];
    float* out = (float*)d_out;

    const int write_extras = ((size_t)out_size >= FULL_OUT) ? 1 : 0;

    cudaFuncSetAttribute(router_mma_kernel,
                         cudaFuncAttributeMaxDynamicSharedMemorySize, SMEM_BYTES);

    prep_kernel<<<256, 256>>>(w, out, write_extras);
    router_mma_kernel<<<TT / BM, NT, SMEM_BYTES>>>(x, noise, out, write_extras);
}